// round 12
// baseline (speedup 1.0000x reference)
#include <cuda_runtime.h>
#include <cuda_bf16.h>
#include <math.h>

#define N_RES 384
#define C_S   384
#define C_Z   128
#define N_HEAD 12
#define CDIM  16
#define N_QP  4
#define N_PV  8
#define NP    1152   // total projection output cols: 192*3 + 144*2 + 288
#define KSPLIT 6     // final GEMM split-K factor (2112 = 6*352, 352 = 11*32)
#define NROWS (N_RES * N_RES)

// ---------------- scratch (device globals; no allocation) ----------------
__device__ __align__(16) float g_proj[N_RES * NP];               // [i][1152]
__device__ __align__(16) float g_Wcat[C_S * NP];                 // concat weights
__device__ __align__(16) float g_bcat[NP];                       // concat biases
__device__ __align__(16) float g_wbhi[C_Z * 16];                 // Wb tf32-hi, [k][n16]
__device__ __align__(16) float g_wblo[C_Z * 16];                 // Wb tf32-lo
__device__ __align__(16) float g_bias[N_HEAD * NROWS];           // [h][i][j]
__device__ __align__(16) float g_att [N_HEAD * NROWS];           // [h][i][j]
__device__ __align__(16) float g_cat [N_RES * 2112];             // concat per residue
__device__ __align__(16) float g_part[KSPLIT * N_RES * C_S];     // split-K partials

// ---------------- tf32 helpers ----------------
__device__ __forceinline__ unsigned f2tf32(float f) {
    unsigned r;
    asm("cvt.rna.tf32.f32 %0, %1;" : "=r"(r) : "f"(f));
    return r;
}
__device__ __forceinline__ void mma_tf32(float* c, const unsigned* a, const unsigned* b) {
    asm("mma.sync.aligned.m16n8k8.row.col.f32.tf32.tf32.f32 "
        "{%0,%1,%2,%3}, {%4,%5,%6,%7}, {%8,%9}, {%0,%1,%2,%3};"
        : "+f"(c[0]), "+f"(c[1]), "+f"(c[2]), "+f"(c[3])
        : "r"(a[0]), "r"(a[1]), "r"(a[2]), "r"(a[3]), "r"(b[0]), "r"(b[1]));
}

// ---------------- prep: concat weights/biases; split Wb into tf32 hi/lo ----------------
__global__ void prep_w(const float* __restrict__ Wq, const float* __restrict__ Wk,
                       const float* __restrict__ Wv, const float* __restrict__ Wqp,
                       const float* __restrict__ Wkp, const float* __restrict__ Wvp,
                       const float* __restrict__ bq, const float* __restrict__ bk,
                       const float* __restrict__ bv, const float* __restrict__ bqp,
                       const float* __restrict__ bkp, const float* __restrict__ bvp,
                       const float* __restrict__ Wb) {
    int idx = blockIdx.x * blockDim.x + threadIdx.x;
    if (idx < C_S * NP) {
        int r = idx / NP, c = idx % NP;
        float w;
        if      (c < 192) w = Wq [r * 192 + c];
        else if (c < 384) w = Wk [r * 192 + c - 192];
        else if (c < 576) w = Wv [r * 192 + c - 384];
        else if (c < 720) w = Wqp[r * 144 + c - 576];
        else if (c < 864) w = Wkp[r * 144 + c - 720];
        else              w = Wvp[r * 288 + c - 864];
        g_Wcat[idx] = w;
    } else if (idx < C_S * NP + NP) {
        int c = idx - C_S * NP;
        float b;
        if      (c < 192) b = bq [c];
        else if (c < 384) b = bk [c - 192];
        else if (c < 576) b = bv [c - 384];
        else if (c < 720) b = bqp[c - 576];
        else if (c < 864) b = bkp[c - 720];
        else              b = bvp[c - 864];
        g_bcat[c] = b;
    } else if (idx < C_S * NP + NP + C_Z * 16) {
        int e = idx - (C_S * NP + NP);
        int k = e >> 4, n = e & 15;
        float w = (n < N_HEAD) ? Wb[k * N_HEAD + n] : 0.f;
        float hi = __uint_as_float(f2tf32(w));
        g_wbhi[e] = hi;
        g_wblo[e] = __uint_as_float(f2tf32(w - hi));
    }
}

// ---------------- tf32 GEMM (3xTF32): C = A(128-tile x K) @ B(K x 64-tile) ----------------
__global__ void gemm_tf32(const float* __restrict__ A, int lda,
                          const float* __restrict__ B, int ldb,
                          const float* __restrict__ bias,
                          float* __restrict__ C, int ldc,
                          int kPerSplit) {
    __shared__ float As[128][36];
    __shared__ float Bs[32][68];
    int tid = threadIdx.x;          // 256
    int warp = tid >> 5, lane = tid & 31;
    int wm = (warp >> 1) * 32;
    int wn = (warp & 1) * 32;
    int row0 = blockIdx.y * 128, col0 = blockIdx.x * 64;
    int kb = blockIdx.z * kPerSplit;
    C += (size_t)blockIdx.z * N_RES * ldc;
    float acc[2][4][4] = {};
    int lm = lane >> 2, lk = lane & 3;
    for (int kt = 0; kt < kPerSplit; kt += 32) {
        #pragma unroll
        for (int l = 0; l < 4; l++) {
            int idx = tid + l * 256;
            int r = idx >> 3, kc = (idx & 7) * 4;
            float4 a4 = *(const float4*)&A[(size_t)(row0 + r) * lda + kb + kt + kc];
            *(float4*)&As[r][kc] = a4;
        }
        #pragma unroll
        for (int l = 0; l < 2; l++) {
            int idx = tid + l * 256;
            int r = idx >> 4, nc = (idx & 15) * 4;
            float4 b4 = *(const float4*)&B[(size_t)(kb + kt + r) * ldb + col0 + nc];
            *(float4*)&Bs[r][nc] = b4;
        }
        __syncthreads();
        #pragma unroll
        for (int k8 = 0; k8 < 32; k8 += 8) {
            unsigned ah[2][4], al[2][4], bh[4][2], bl[4][2];
            #pragma unroll
            for (int mf = 0; mf < 2; mf++) {
                int m = wm + mf * 16 + lm;
                float v0 = As[m][k8 + lk];
                float v1 = As[m + 8][k8 + lk];
                float v2 = As[m][k8 + 4 + lk];
                float v3 = As[m + 8][k8 + 4 + lk];
                ah[mf][0] = f2tf32(v0); al[mf][0] = f2tf32(v0 - __uint_as_float(ah[mf][0]));
                ah[mf][1] = f2tf32(v1); al[mf][1] = f2tf32(v1 - __uint_as_float(ah[mf][1]));
                ah[mf][2] = f2tf32(v2); al[mf][2] = f2tf32(v2 - __uint_as_float(ah[mf][2]));
                ah[mf][3] = f2tf32(v3); al[mf][3] = f2tf32(v3 - __uint_as_float(ah[mf][3]));
            }
            #pragma unroll
            for (int nf = 0; nf < 4; nf++) {
                int n = wn + nf * 8 + lm;
                float w0 = Bs[k8 + lk][n];
                float w1 = Bs[k8 + 4 + lk][n];
                bh[nf][0] = f2tf32(w0); bl[nf][0] = f2tf32(w0 - __uint_as_float(bh[nf][0]));
                bh[nf][1] = f2tf32(w1); bl[nf][1] = f2tf32(w1 - __uint_as_float(bh[nf][1]));
            }
            #pragma unroll
            for (int mf = 0; mf < 2; mf++) {
                #pragma unroll
                for (int nf = 0; nf < 4; nf++) {
                    mma_tf32(acc[mf][nf], al[mf], bh[nf]);
                    mma_tf32(acc[mf][nf], ah[mf], bl[nf]);
                    mma_tf32(acc[mf][nf], ah[mf], bh[nf]);
                }
            }
        }
        __syncthreads();
    }
    #pragma unroll
    for (int mf = 0; mf < 2; mf++) {
        #pragma unroll
        for (int nf = 0; nf < 4; nf++) {
            int r = row0 + wm + mf * 16 + lm;
            int c = col0 + wn + nf * 8 + lk * 2;
            float2 v0 = make_float2(acc[mf][nf][0], acc[mf][nf][1]);
            float2 v1 = make_float2(acc[mf][nf][2], acc[mf][nf][3]);
            if (bias != nullptr) {
                float b0 = bias[c], b1 = bias[c + 1];
                v0.x += b0; v0.y += b1; v1.x += b0; v1.y += b1;
            }
            *(float2*)&C[(size_t)r * ldc + c] = v0;
            *(float2*)&C[(size_t)(r + 8) * ldc + c] = v1;
        }
    }
}

// ---------------- reduce split-K partials + bias -> out ----------------
__global__ void reduce_out(const float* __restrict__ bo, float* __restrict__ out) {
    int idx = blockIdx.x * blockDim.x + threadIdx.x;
    if (idx >= N_RES * C_S / 4) return;
    const float4* p = (const float4*)g_part;
    float4 r = p[idx];
    #pragma unroll
    for (int s = 1; s < KSPLIT; s++) {
        float4 q = p[idx + s * (N_RES * C_S / 4)];
        r.x += q.x; r.y += q.y; r.z += q.z; r.w += q.w;
    }
    int col = (idx * 4) % C_S;
    r.x += bo[col]; r.y += bo[col + 1]; r.z += bo[col + 2]; r.w += bo[col + 3];
    ((float4*)out)[idx] = r;
}

// ---------------- bias = moveaxis(z @ Wb + bb) via m16n8k8 3xTF32 ----------------
__global__ void bias_mma(const float* __restrict__ z, const float* __restrict__ bb) {
    __shared__ float bhs[C_Z][16];
    __shared__ float bls[C_Z][16];
    __shared__ float cbuf[128][17];
    int tid = threadIdx.x;             // 256
    for (int e = tid; e < C_Z * 16; e += 256) {
        bhs[e >> 4][e & 15] = g_wbhi[e];
        bls[e >> 4][e & 15] = g_wblo[e];
    }
    __syncthreads();
    int warp = tid >> 5, lane = tid & 31;
    int lm = lane >> 2, lk = lane & 3;
    int row0 = blockIdx.x * 128 + warp * 16;
    const float* zr0 = z + (size_t)(row0 + lm) * C_Z;
    const float* zr1 = z + (size_t)(row0 + lm + 8) * C_Z;
    float acc[2][4] = {};
    #pragma unroll
    for (int k8 = 0; k8 < C_Z; k8 += 8) {
        float a0f = zr0[k8 + lk];
        float a1f = zr1[k8 + lk];
        float a2f = zr0[k8 + 4 + lk];
        float a3f = zr1[k8 + 4 + lk];
        unsigned ah[4], al[4];
        ah[0] = f2tf32(a0f); al[0] = f2tf32(a0f - __uint_as_float(ah[0]));
        ah[1] = f2tf32(a1f); al[1] = f2tf32(a1f - __uint_as_float(ah[1]));
        ah[2] = f2tf32(a2f); al[2] = f2tf32(a2f - __uint_as_float(ah[2]));
        ah[3] = f2tf32(a3f); al[3] = f2tf32(a3f - __uint_as_float(ah[3]));
        #pragma unroll
        for (int g = 0; g < 2; g++) {
            unsigned bhf[2], blf[2];
            bhf[0] = __float_as_uint(bhs[k8 + lk][g * 8 + lm]);
            bhf[1] = __float_as_uint(bhs[k8 + 4 + lk][g * 8 + lm]);
            blf[0] = __float_as_uint(bls[k8 + lk][g * 8 + lm]);
            blf[1] = __float_as_uint(bls[k8 + 4 + lk][g * 8 + lm]);
            mma_tf32(acc[g], al, bhf);
            mma_tf32(acc[g], ah, blf);
            mma_tf32(acc[g], ah, bhf);
        }
    }
    #pragma unroll
    for (int g = 0; g < 2; g++) {
        cbuf[warp * 16 + lm][g * 8 + lk * 2]         = acc[g][0];
        cbuf[warp * 16 + lm][g * 8 + lk * 2 + 1]     = acc[g][1];
        cbuf[warp * 16 + lm + 8][g * 8 + lk * 2]     = acc[g][2];
        cbuf[warp * 16 + lm + 8][g * 8 + lk * 2 + 1] = acc[g][3];
    }
    __syncthreads();
    int base = blockIdx.x * 128;
    for (int e = tid; e < N_HEAD * 128; e += 256) {
        int h = e >> 7, r = e & 127;
        g_bias[(size_t)h * NROWS + base + r] = cbuf[r][h] + bb[h];
    }
}

// ---------------- tiled attention (frames applied inline): block per (h, 32-row i-tile) ----------------
__global__ void attn_fused(const float* __restrict__ hw, const float* __restrict__ Tg) {
    const float WL  = 0.5773502691896258f;
    const float WC2 = 0.11785113019775793f;
    int h = blockIdx.y;
    int i0 = blockIdx.x * 32;
    int tid = threadIdx.x;   // 256
    __shared__ float ks [CDIM][N_RES];       // 24 KB
    __shared__ float tks[12][N_RES];         // 18 KB
    __shared__ float qs [32][CDIM];          // 2 KB
    __shared__ float tqs[32][12];            // 1.5 KB
    // k for this head, transposed (SoA over j)
    for (int t = tid; t < N_RES * 4; t += 256) {
        int j = t >> 2, cq = (t & 3) * 4;
        float4 kv = *(const float4*)&g_proj[(size_t)j * NP + 192 + h * CDIM + cq];
        ks[cq + 0][j] = kv.x; ks[cq + 1][j] = kv.y;
        ks[cq + 2][j] = kv.z; ks[cq + 3][j] = kv.w;
    }
    // tk built inline: warp_3d_point(T_j, kp_j) per (pd, j)
    for (int t = tid; t < 12 * N_RES; t += 256) {
        int pd = t / N_RES, j = t % N_RES;
        int p = pd / 3, d = pd % 3;
        const float* pj = &g_proj[(size_t)j * NP + 720 + h * N_QP + p];
        float lx = pj[0], ly = pj[48], lz = pj[96];
        float4 Tr = *(const float4*)&Tg[j * 16 + d * 4];
        tks[pd][j] = Tr.x * lx + Tr.y * ly + Tr.z * lz + Tr.w;
    }
    // q (scaled)
    for (int t = tid; t < 32 * CDIM; t += 256) {
        int il = t / CDIM, c = t % CDIM;
        qs[il][c] = g_proj[(size_t)(i0 + il) * NP + h * CDIM + c] * 0.25f;
    }
    // tq built inline
    for (int t = tid; t < 32 * 12; t += 256) {
        int il = t / 12, pd = t % 12;
        int p = pd / 3, d = pd % 3;
        int i = i0 + il;
        const float* pi = &g_proj[(size_t)i * NP + 576 + h * N_QP + p];
        float4 Tr = *(const float4*)&Tg[i * 16 + d * 4];
        tqs[il][pd] = Tr.x * pi[0] + Tr.y * pi[48] + Tr.z * pi[96] + Tr.w;
    }
    __syncthreads();
    float gam = log1pf(__expf(hw[h]));
    float coef = gam * WC2;
    int w = tid >> 5, lane = tid & 31;
    #pragma unroll
    for (int rr = 0; rr < 4; rr++) {
        int il = w * 4 + rr;
        int i = i0 + il;
        const float* brow = &g_bias[((size_t)h * N_RES + i) * N_RES];
        float lreg[12];
        float lmax = -1e30f;
        #pragma unroll
        for (int jj = 0; jj < 12; jj++) {
            int j = lane + jj * 32;
            float qk = 0.f;
            #pragma unroll
            for (int c = 0; c < CDIM; c++) qk += qs[il][c] * ks[c][j];
            float dist = 0.f;
            #pragma unroll
            for (int pd = 0; pd < 12; pd++) {
                float dlt = tqs[il][pd] - tks[pd][j];
                dist += dlt * dlt;
            }
            float lg = WL * (qk + brow[j] - coef * dist);
            lreg[jj] = lg;
            lmax = fmaxf(lmax, lg);
        }
        #pragma unroll
        for (int off = 16; off > 0; off >>= 1)
            lmax = fmaxf(lmax, __shfl_xor_sync(0xffffffffu, lmax, off));
        float s = 0.f;
        #pragma unroll
        for (int jj = 0; jj < 12; jj++) {
            float e = __expf(lreg[jj] - lmax);
            lreg[jj] = e;
            s += e;
        }
        #pragma unroll
        for (int off = 16; off > 0; off >>= 1)
            s += __shfl_xor_sync(0xffffffffu, s, off);
        float inv = 1.f / s;
        float* arow = &g_att[((size_t)h * N_RES + i) * N_RES];
        #pragma unroll
        for (int jj = 0; jj < 12; jj++)
            arow[lane + jj * 32] = lreg[jj] * inv;
    }
}

// ---------------- pairwise: block per (i, c-half) ----------------
__global__ void pairwise_kernel(const float* __restrict__ z) {
    int i = blockIdx.x;
    int ch = blockIdx.y;
    int tid = threadIdx.x;   // 256
    __shared__ float att_s[N_HEAD][N_RES];
    __shared__ float4 part[8][N_HEAD][16];
    for (int idx = tid; idx < N_HEAD * N_RES; idx += 256) {
        int h = idx / N_RES, j = idx % N_RES;
        att_s[h][j] = g_att[((size_t)h * N_RES + i) * N_RES + j];
    }
    __syncthreads();
    int c4 = tid & 15;
    int jr = tid >> 4;
    const float4* zp = (const float4*)(z + (size_t)i * N_RES * C_Z) + ch * 16 + c4;
    float acc[N_HEAD][4];
    #pragma unroll
    for (int h = 0; h < N_HEAD; h++) {
        acc[h][0] = 0.f; acc[h][1] = 0.f; acc[h][2] = 0.f; acc[h][3] = 0.f;
    }
    for (int j = jr; j < N_RES; j += 16) {
        float4 zv = zp[j * 32];
        #pragma unroll
        for (int h = 0; h < N_HEAD; h++) {
            float a = att_s[h][j];
            acc[h][0] += a * zv.x; acc[h][1] += a * zv.y;
            acc[h][2] += a * zv.z; acc[h][3] += a * zv.w;
        }
    }
    #pragma unroll
    for (int h = 0; h < N_HEAD; h++) {
        #pragma unroll
        for (int q = 0; q < 4; q++)
            acc[h][q] += __shfl_xor_sync(0xffffffffu, acc[h][q], 16);
    }
    int w = tid >> 5;
    if ((tid & 16) == 0) {
        #pragma unroll
        for (int h = 0; h < N_HEAD; h++)
            part[w][h][c4] = make_float4(acc[h][0], acc[h][1], acc[h][2], acc[h][3]);
    }
    __syncthreads();
    if (tid < N_HEAD * 16) {
        int h = tid >> 4, cc = tid & 15;
        float4 r = part[0][h][cc];
        #pragma unroll
        for (int w2 = 1; w2 < 8; w2++) {
            float4 q = part[w2][h][cc];
            r.x += q.x; r.y += q.y; r.z += q.z; r.w += q.w;
        }
        *(float4*)&g_cat[(size_t)i * 2112 + 576 + h * C_Z + ch * 64 + cc * 4] = r;
    }
}

// ---------------- eo = att[h] @ [v|vt] (vt built inline), fused inverse warp/norm/concat ----------------
__global__ void vatt_post(const float* __restrict__ Tg) {
    int h = blockIdx.y;
    int i0 = blockIdx.x * 32;
    __shared__ float at[32][33];
    __shared__ float vc[32][41];
    __shared__ float eo_s[32][41];
    int tid = threadIdx.x;   // 320
    int col = tid % 40, rgrp = tid / 40;
    float acc[4] = {0.f, 0.f, 0.f, 0.f};
    for (int j0 = 0; j0 < N_RES; j0 += 32) {
        for (int idx = tid; idx < 1024; idx += 320) {
            int r = idx / 32, c = idx % 32;
            at[r][c] = g_att[((size_t)h * N_RES + i0 + r) * N_RES + j0 + c];
        }
        // build [v | warp(T_j, vp_j)] tile inline from proj + T
        for (int idx = tid; idx < 1280; idx += 320) {
            int r = idx / 40, c = idx % 40;
            int j = j0 + r;
            float val;
            if (c < CDIM) {
                val = g_proj[(size_t)j * NP + 384 + h * CDIM + c];
            } else {
                int k = (c - CDIM) / 3, d = (c - CDIM) % 3;
                const float* pj = &g_proj[(size_t)j * NP + 864 + h * N_PV + k];
                float4 Tr = *(const float4*)&Tg[j * 16 + d * 4];
                val = Tr.x * pj[0] + Tr.y * pj[96] + Tr.z * pj[192] + Tr.w;
            }
            vc[r][c] = val;
        }
        __syncthreads();
        #pragma unroll 8
        for (int jj = 0; jj < 32; jj++) {
            float b = vc[jj][col];
            #pragma unroll
            for (int rr = 0; rr < 4; rr++) acc[rr] += at[rgrp + rr * 8][jj] * b;
        }
        __syncthreads();
    }
    #pragma unroll
    for (int rr = 0; rr < 4; rr++)
        eo_s[rgrp + rr * 8][col] = acc[rr];
    __syncthreads();
    if (tid < 32) {
        int i = i0 + tid;
        const float* e = eo_s[tid];
        float* catp = &g_cat[(size_t)i * 2112];
        #pragma unroll
        for (int c = 0; c < CDIM; c++) catp[h * CDIM + c] = e[c];
        float R[9], tv[3];
        #pragma unroll
        for (int d = 0; d < 9; d++) R[d] = Tg[i * 16 + (d / 3) * 4 + (d % 3)];
        #pragma unroll
        for (int d = 0; d < 3; d++) tv[d] = Tg[i * 16 + d * 4 + 3];
        #pragma unroll
        for (int k = 0; k < N_PV; k++) {
            float px = e[16 + k * 3 + 0] - tv[0];
            float py = e[16 + k * 3 + 1] - tv[1];
            float pz = e[16 + k * 3 + 2] - tv[2];
            float lx = R[0] * px + R[3] * py + R[6] * pz;
            float ly = R[1] * px + R[4] * py + R[7] * pz;
            float lz = R[2] * px + R[5] * py + R[8] * pz;
            catp[192 + 0 * 96 + h * N_PV + k] = lx;
            catp[192 + 1 * 96 + h * N_PV + k] = ly;
            catp[192 + 2 * 96 + h * N_PV + k] = lz;
            catp[480 + h * N_PV + k] = sqrtf(lx * lx + ly * ly + lz * lz);
        }
    }
}

extern "C" void kernel_launch(void* const* d_in, const int* in_sizes, int n_in,
                              void* d_out, int out_size) {
    const float* s   = (const float*)d_in[0];
    const float* z   = (const float*)d_in[1];
    const float* T   = (const float*)d_in[2];
    const float* Wq  = (const float*)d_in[3];
    const float* bq  = (const float*)d_in[4];
    const float* Wk  = (const float*)d_in[5];
    const float* bk  = (const float*)d_in[6];
    const float* Wv  = (const float*)d_in[7];
    const float* bv  = (const float*)d_in[8];
    const float* Wqp = (const float*)d_in[9];
    const float* bqp = (const float*)d_in[10];
    const float* Wkp = (const float*)d_in[11];
    const float* bkp = (const float*)d_in[12];
    const float* Wvp = (const float*)d_in[13];
    const float* bvp = (const float*)d_in[14];
    const float* Wb  = (const float*)d_in[15];
    const float* bb  = (const float*)d_in[16];
    const float* Wo  = (const float*)d_in[17];
    const float* bo  = (const float*)d_in[18];
    const float* hw  = (const float*)d_in[19];
    float* out = (float*)d_out;

    float *p_proj, *p_Wcat, *p_bcat, *p_cat, *p_part;
    cudaGetSymbolAddress((void**)&p_proj, g_proj);
    cudaGetSymbolAddress((void**)&p_Wcat, g_Wcat);
    cudaGetSymbolAddress((void**)&p_bcat, g_bcat);
    cudaGetSymbolAddress((void**)&p_cat,  g_cat);
    cudaGetSymbolAddress((void**)&p_part, g_part);

    // 1) concat weights + Wb tf32 split
    prep_w<<<(C_S * NP + NP + C_Z * 16 + 255) / 256, 256>>>(Wq, Wk, Wv, Wqp, Wkp, Wvp,
                                                            bq, bk, bv, bqp, bkp, bvp, Wb);
    // 2) all six projections in one tf32 GEMM: s(384x384) @ Wcat(384x1152)
    gemm_tf32<<<dim3(NP / 64, N_RES / 128, 1), 256>>>(s, C_S, p_Wcat, NP, p_bcat, p_proj, NP, C_S);
    // 3) bias from z via tensor cores (75 MB stream)
    bias_mma<<<NROWS / 128, 256>>>(z, bb);
    // 4) tiled attention + softmax (frames applied inline)  <-- profiled slot
    attn_fused<<<dim3(N_RES / 32, N_HEAD), 256>>>(hw, T);
    // 5) pairwise (writes cat[576:2112)) — second 75 MB z stream, c-split x2
    pairwise_kernel<<<dim3(N_RES, 2), 256>>>(z);
    // 6) att @ [v|vt] (vt inline) + fused inverse warp/norm/concat (writes cat[0:576))
    vatt_post<<<dim3(12, 12), 320>>>(T);
    // 7) final projection: cat(384x2112) @ Wo(2112x384), tf32 split-K=6
    gemm_tf32<<<dim3(C_S / 64, N_RES / 128, KSPLIT), 256>>>(p_cat, 2112, Wo, C_S, nullptr, p_part, C_S, 2112 / KSPLIT);
    reduce_out<<<(N_RES * C_S / 4 + 255) / 256, 256>>>(bo, out);
}

// round 13
// speedup vs baseline: 1.3905x; 1.3905x over previous
#include <cuda_runtime.h>
#include <cuda_bf16.h>
#include <math.h>

#define N_RES 384
#define C_S   384
#define C_Z   128
#define N_HEAD 12
#define CDIM  16
#define N_QP  4
#define N_PV  8
#define NP    1152   // total projection output cols: 192*3 + 144*2 + 288
#define KSPLIT 6     // final GEMM split-K factor
#define NROWS (N_RES * N_RES)
// bias_mma dynamic smem: bhs(2048) + bls(2048) + cbuf(128*17=2176) + zt(8*16*132=16896) floats
#define BIAS_SMEM_FLOATS (2048 + 2048 + 2176 + 16896)
#define BIAS_SMEM_BYTES  (BIAS_SMEM_FLOATS * 4)

// ---------------- scratch (device globals; no allocation) ----------------
__device__ __align__(16) float g_proj[N_RES * NP];               // [i][1152]
__device__ __align__(16) float g_Wcat[C_S * NP];                 // concat weights
__device__ __align__(16) float g_bcat[NP];                       // concat biases
__device__ __align__(16) float g_wbhi[C_Z * 16];                 // Wb tf32-hi, [k][n16]
__device__ __align__(16) float g_wblo[C_Z * 16];                 // Wb tf32-lo
__device__ __align__(16) float g_bias[N_HEAD * NROWS];           // [h][i][j]
__device__ __align__(16) float g_att [N_HEAD * NROWS];           // [h][i][j]
__device__ __align__(16) float g_cat [N_RES * 2112];             // concat per residue
__device__ __align__(16) float g_part[KSPLIT * N_RES * C_S];     // split-K partials

// ---------------- tf32 helpers ----------------
__device__ __forceinline__ unsigned f2tf32(float f) {
    unsigned r;
    asm("cvt.rna.tf32.f32 %0, %1;" : "=r"(r) : "f"(f));
    return r;
}
__device__ __forceinline__ void mma_tf32(float* c, const unsigned* a, const unsigned* b) {
    asm("mma.sync.aligned.m16n8k8.row.col.f32.tf32.tf32.f32 "
        "{%0,%1,%2,%3}, {%4,%5,%6,%7}, {%8,%9}, {%0,%1,%2,%3};"
        : "+f"(c[0]), "+f"(c[1]), "+f"(c[2]), "+f"(c[3])
        : "r"(a[0]), "r"(a[1]), "r"(a[2]), "r"(a[3]), "r"(b[0]), "r"(b[1]));
}

// ---------------- prep: concat weights/biases; split Wb into tf32 hi/lo ----------------
__global__ void prep_w(const float* __restrict__ Wq, const float* __restrict__ Wk,
                       const float* __restrict__ Wv, const float* __restrict__ Wqp,
                       const float* __restrict__ Wkp, const float* __restrict__ Wvp,
                       const float* __restrict__ bq, const float* __restrict__ bk,
                       const float* __restrict__ bv, const float* __restrict__ bqp,
                       const float* __restrict__ bkp, const float* __restrict__ bvp,
                       const float* __restrict__ Wb) {
    int idx = blockIdx.x * blockDim.x + threadIdx.x;
    if (idx < C_S * NP) {
        int r = idx / NP, c = idx % NP;
        float w;
        if      (c < 192) w = Wq [r * 192 + c];
        else if (c < 384) w = Wk [r * 192 + c - 192];
        else if (c < 576) w = Wv [r * 192 + c - 384];
        else if (c < 720) w = Wqp[r * 144 + c - 576];
        else if (c < 864) w = Wkp[r * 144 + c - 720];
        else              w = Wvp[r * 288 + c - 864];
        g_Wcat[idx] = w;
    } else if (idx < C_S * NP + NP) {
        int c = idx - C_S * NP;
        float b;
        if      (c < 192) b = bq [c];
        else if (c < 384) b = bk [c - 192];
        else if (c < 576) b = bv [c - 384];
        else if (c < 720) b = bqp[c - 576];
        else if (c < 864) b = bkp[c - 720];
        else              b = bvp[c - 864];
        g_bcat[c] = b;
    } else if (idx < C_S * NP + NP + C_Z * 16) {
        int e = idx - (C_S * NP + NP);
        int k = e >> 4, n = e & 15;
        float w = (n < N_HEAD) ? Wb[k * N_HEAD + n] : 0.f;
        float hi = __uint_as_float(f2tf32(w));
        g_wbhi[e] = hi;
        g_wblo[e] = __uint_as_float(f2tf32(w - hi));
    }
}

// ---------------- tf32 GEMM (3xTF32): C = A(128-tile x K) @ B(K x 64-tile) ----------------
__global__ void gemm_tf32(const float* __restrict__ A, int lda,
                          const float* __restrict__ B, int ldb,
                          const float* __restrict__ bias,
                          float* __restrict__ C, int ldc,
                          int kPerSplit) {
    __shared__ float As[128][36];
    __shared__ float Bs[32][68];
    int tid = threadIdx.x;          // 256
    int warp = tid >> 5, lane = tid & 31;
    int wm = (warp >> 1) * 32;
    int wn = (warp & 1) * 32;
    int row0 = blockIdx.y * 128, col0 = blockIdx.x * 64;
    int kb = blockIdx.z * kPerSplit;
    C += (size_t)blockIdx.z * N_RES * ldc;
    float acc[2][4][4] = {};
    int lm = lane >> 2, lk = lane & 3;
    for (int kt = 0; kt < kPerSplit; kt += 32) {
        #pragma unroll
        for (int l = 0; l < 4; l++) {
            int idx = tid + l * 256;
            int r = idx >> 3, kc = (idx & 7) * 4;
            float4 a4 = *(const float4*)&A[(size_t)(row0 + r) * lda + kb + kt + kc];
            *(float4*)&As[r][kc] = a4;
        }
        #pragma unroll
        for (int l = 0; l < 2; l++) {
            int idx = tid + l * 256;
            int r = idx >> 4, nc = (idx & 15) * 4;
            float4 b4 = *(const float4*)&B[(size_t)(kb + kt + r) * ldb + col0 + nc];
            *(float4*)&Bs[r][nc] = b4;
        }
        __syncthreads();
        #pragma unroll
        for (int k8 = 0; k8 < 32; k8 += 8) {
            unsigned ah[2][4], al[2][4], bh[4][2], bl[4][2];
            #pragma unroll
            for (int mf = 0; mf < 2; mf++) {
                int m = wm + mf * 16 + lm;
                float v0 = As[m][k8 + lk];
                float v1 = As[m + 8][k8 + lk];
                float v2 = As[m][k8 + 4 + lk];
                float v3 = As[m + 8][k8 + 4 + lk];
                ah[mf][0] = f2tf32(v0); al[mf][0] = f2tf32(v0 - __uint_as_float(ah[mf][0]));
                ah[mf][1] = f2tf32(v1); al[mf][1] = f2tf32(v1 - __uint_as_float(ah[mf][1]));
                ah[mf][2] = f2tf32(v2); al[mf][2] = f2tf32(v2 - __uint_as_float(ah[mf][2]));
                ah[mf][3] = f2tf32(v3); al[mf][3] = f2tf32(v3 - __uint_as_float(ah[mf][3]));
            }
            #pragma unroll
            for (int nf = 0; nf < 4; nf++) {
                int n = wn + nf * 8 + lm;
                float w0 = Bs[k8 + lk][n];
                float w1 = Bs[k8 + 4 + lk][n];
                bh[nf][0] = f2tf32(w0); bl[nf][0] = f2tf32(w0 - __uint_as_float(bh[nf][0]));
                bh[nf][1] = f2tf32(w1); bl[nf][1] = f2tf32(w1 - __uint_as_float(bh[nf][1]));
            }
            #pragma unroll
            for (int mf = 0; mf < 2; mf++) {
                #pragma unroll
                for (int nf = 0; nf < 4; nf++) {
                    mma_tf32(acc[mf][nf], al[mf], bh[nf]);
                    mma_tf32(acc[mf][nf], ah[mf], bl[nf]);
                    mma_tf32(acc[mf][nf], ah[mf], bh[nf]);
                }
            }
        }
        __syncthreads();
    }
    #pragma unroll
    for (int mf = 0; mf < 2; mf++) {
        #pragma unroll
        for (int nf = 0; nf < 4; nf++) {
            int r = row0 + wm + mf * 16 + lm;
            int c = col0 + wn + nf * 8 + lk * 2;
            float2 v0 = make_float2(acc[mf][nf][0], acc[mf][nf][1]);
            float2 v1 = make_float2(acc[mf][nf][2], acc[mf][nf][3]);
            if (bias != nullptr) {
                float b0 = bias[c], b1 = bias[c + 1];
                v0.x += b0; v0.y += b1; v1.x += b0; v1.y += b1;
            }
            *(float2*)&C[(size_t)r * ldc + c] = v0;
            *(float2*)&C[(size_t)(r + 8) * ldc + c] = v1;
        }
    }
}

// ---------------- reduce split-K partials + bias -> out ----------------
__global__ void reduce_out(const float* __restrict__ bo, float* __restrict__ out) {
    int idx = blockIdx.x * blockDim.x + threadIdx.x;
    if (idx >= N_RES * C_S / 4) return;
    const float4* p = (const float4*)g_part;
    float4 r = p[idx];
    #pragma unroll
    for (int s = 1; s < KSPLIT; s++) {
        float4 q = p[idx + s * (N_RES * C_S / 4)];
        r.x += q.x; r.y += q.y; r.z += q.z; r.w += q.w;
    }
    int col = (idx * 4) % C_S;
    r.x += bo[col]; r.y += bo[col + 1]; r.z += bo[col + 2]; r.w += bo[col + 3];
    ((float4*)out)[idx] = r;
}

// ---------------- bias = moveaxis(z @ Wb + bb) via m16n8k8 3xTF32, smem-staged z ----------------
__global__ void bias_mma(const float* __restrict__ z, const float* __restrict__ bb) {
    extern __shared__ float dyn[];
    float* bhs  = dyn;                       // [C_Z][16]
    float* bls  = bhs + C_Z * 16;            // [C_Z][16]
    float* cbuf = bls + C_Z * 16;            // [128][17]
    float* zt   = cbuf + 128 * 17;           // [8][16][132]
    int tid = threadIdx.x;                   // 256
    for (int e = tid; e < C_Z * 16; e += 256) {
        bhs[e] = g_wbhi[e];
        bls[e] = g_wblo[e];
    }
    int warp = tid >> 5, lane = tid & 31;
    int lm = lane >> 2, lk = lane & 3;
    int row0 = blockIdx.x * 128 + warp * 16;
    float* ztw = zt + warp * 16 * 132;
    // stage this warp's 16x128 z tile, coalesced float4
    #pragma unroll
    for (int r = 0; r < 16; r++) {
        float4 v = *(const float4*)&z[(size_t)(row0 + r) * C_Z + lane * 4];
        *(float4*)&ztw[r * 132 + lane * 4] = v;
    }
    __syncthreads();
    float acc[2][4] = {};
    #pragma unroll
    for (int k8 = 0; k8 < C_Z; k8 += 8) {
        float a0f = ztw[lm * 132 + k8 + lk];
        float a1f = ztw[(lm + 8) * 132 + k8 + lk];
        float a2f = ztw[lm * 132 + k8 + 4 + lk];
        float a3f = ztw[(lm + 8) * 132 + k8 + 4 + lk];
        unsigned ah[4], al[4];
        ah[0] = f2tf32(a0f); al[0] = f2tf32(a0f - __uint_as_float(ah[0]));
        ah[1] = f2tf32(a1f); al[1] = f2tf32(a1f - __uint_as_float(ah[1]));
        ah[2] = f2tf32(a2f); al[2] = f2tf32(a2f - __uint_as_float(ah[2]));
        ah[3] = f2tf32(a3f); al[3] = f2tf32(a3f - __uint_as_float(ah[3]));
        #pragma unroll
        for (int g = 0; g < 2; g++) {
            unsigned bhf[2], blf[2];
            bhf[0] = __float_as_uint(bhs[(k8 + lk) * 16 + g * 8 + lm]);
            bhf[1] = __float_as_uint(bhs[(k8 + 4 + lk) * 16 + g * 8 + lm]);
            blf[0] = __float_as_uint(bls[(k8 + lk) * 16 + g * 8 + lm]);
            blf[1] = __float_as_uint(bls[(k8 + 4 + lk) * 16 + g * 8 + lm]);
            mma_tf32(acc[g], al, bhf);
            mma_tf32(acc[g], ah, blf);
            mma_tf32(acc[g], ah, bhf);
        }
    }
    #pragma unroll
    for (int g = 0; g < 2; g++) {
        cbuf[(warp * 16 + lm) * 17 + g * 8 + lk * 2]           = acc[g][0];
        cbuf[(warp * 16 + lm) * 17 + g * 8 + lk * 2 + 1]       = acc[g][1];
        cbuf[(warp * 16 + lm + 8) * 17 + g * 8 + lk * 2]       = acc[g][2];
        cbuf[(warp * 16 + lm + 8) * 17 + g * 8 + lk * 2 + 1]   = acc[g][3];
    }
    __syncthreads();
    int base = blockIdx.x * 128;
    for (int e = tid; e < N_HEAD * 128; e += 256) {
        int h = e >> 7, r = e & 127;
        g_bias[(size_t)h * NROWS + base + r] = cbuf[r * 17 + h] + bb[h];
    }
}

// ---------------- tiled attention, expanded-distance form: block per (h, 32-row i-tile) ----------------
__global__ __launch_bounds__(256, 2) void attn_fused(const float* __restrict__ hw,
                                                     const float* __restrict__ Tg) {
    const float WL  = 0.5773502691896258f;   // sqrt(1/3)
    const float WC2 = 0.11785113019775793f;  // sqrt(2/(9*4))/2
    int h = blockIdx.y;
    int i0 = blockIdx.x * 32;
    int tid = threadIdx.x;   // 256
    __shared__ float ks [CDIM][N_RES];       // 24 KB   k values
    __shared__ float cks[12][N_RES];         // 18 KB   2*coef*tk
    __shared__ float bj [N_RES];             // 1.5 KB  -coef*|tk|^2
    __shared__ float qs [32][CDIM];          // 2 KB    q * 1/sqrt(C)
    __shared__ float tqs[32][12];            // 1.5 KB  tq
    float gam = log1pf(__expf(hw[h]));
    float coef = gam * WC2;
    float twoCoef = 2.f * coef;
    // k for this head, transposed (SoA over j)
    for (int t = tid; t < N_RES * 4; t += 256) {
        int j = t >> 2, cq = (t & 3) * 4;
        float4 kv = *(const float4*)&g_proj[(size_t)j * NP + 192 + h * CDIM + cq];
        ks[cq + 0][j] = kv.x; ks[cq + 1][j] = kv.y;
        ks[cq + 2][j] = kv.z; ks[cq + 3][j] = kv.w;
    }
    // tk built inline per j: cks = 2*coef*tk, bj = -coef*|tk|^2
    for (int j = tid; j < N_RES; j += 256) {
        float4 T0 = *(const float4*)&Tg[j * 16 + 0];
        float4 T1 = *(const float4*)&Tg[j * 16 + 4];
        float4 T2 = *(const float4*)&Tg[j * 16 + 8];
        float tkk = 0.f;
        #pragma unroll
        for (int p = 0; p < N_QP; p++) {
            const float* pj = &g_proj[(size_t)j * NP + 720 + h * N_QP + p];
            float lx = pj[0], ly = pj[48], lz = pj[96];
            float gx = T0.x * lx + T0.y * ly + T0.z * lz + T0.w;
            float gy = T1.x * lx + T1.y * ly + T1.z * lz + T1.w;
            float gz = T2.x * lx + T2.y * ly + T2.z * lz + T2.w;
            cks[p * 3 + 0][j] = twoCoef * gx;
            cks[p * 3 + 1][j] = twoCoef * gy;
            cks[p * 3 + 2][j] = twoCoef * gz;
            tkk += gx * gx + gy * gy + gz * gz;
        }
        bj[j] = -coef * tkk;
    }
    // q (scaled)
    for (int t = tid; t < 32 * CDIM; t += 256) {
        int il = t / CDIM, c = t % CDIM;
        qs[il][c] = g_proj[(size_t)(i0 + il) * NP + h * CDIM + c] * 0.25f;
    }
    // tq built inline per (il)
    for (int t = tid; t < 32 * N_QP; t += 256) {
        int il = t / N_QP, p = t % N_QP;
        int i = i0 + il;
        float4 T0 = *(const float4*)&Tg[i * 16 + 0];
        float4 T1 = *(const float4*)&Tg[i * 16 + 4];
        float4 T2 = *(const float4*)&Tg[i * 16 + 8];
        const float* pi = &g_proj[(size_t)i * NP + 576 + h * N_QP + p];
        float lx = pi[0], ly = pi[48], lz = pi[96];
        tqs[il][p * 3 + 0] = T0.x * lx + T0.y * ly + T0.z * lz + T0.w;
        tqs[il][p * 3 + 1] = T1.x * lx + T1.y * ly + T1.z * lz + T1.w;
        tqs[il][p * 3 + 2] = T2.x * lx + T2.y * ly + T2.z * lz + T2.w;
    }
    __syncthreads();
    int w = tid >> 5, lane = tid & 31;
    for (int rr = 0; rr < 4; rr++) {          // NOT unrolled: keeps regs low
        int il = w * 4 + rr;
        int i = i0 + il;
        float ctqq = 0.f;
        #pragma unroll
        for (int pd = 0; pd < 12; pd++) {
            float tq = tqs[il][pd];
            ctqq += tq * tq;
        }
        ctqq *= coef;
        const float* brow = &g_bias[((size_t)h * N_RES + i) * N_RES];
        float lreg[12];
        float lmax = -1e30f;
        #pragma unroll
        for (int jj = 0; jj < 12; jj++) {
            int j = lane + jj * 32;
            float acc = brow[j] + bj[j] - ctqq;
            #pragma unroll
            for (int c = 0; c < CDIM; c++) acc += qs[il][c] * ks[c][j];
            #pragma unroll
            for (int pd = 0; pd < 12; pd++) acc += tqs[il][pd] * cks[pd][j];
            float lg = WL * acc;
            lreg[jj] = lg;
            lmax = fmaxf(lmax, lg);
        }
        #pragma unroll
        for (int off = 16; off > 0; off >>= 1)
            lmax = fmaxf(lmax, __shfl_xor_sync(0xffffffffu, lmax, off));
        float s = 0.f;
        #pragma unroll
        for (int jj = 0; jj < 12; jj++) {
            float e = __expf(lreg[jj] - lmax);
            lreg[jj] = e;
            s += e;
        }
        #pragma unroll
        for (int off = 16; off > 0; off >>= 1)
            s += __shfl_xor_sync(0xffffffffu, s, off);
        float inv = 1.f / s;
        float* arow = &g_att[((size_t)h * N_RES + i) * N_RES];
        #pragma unroll
        for (int jj = 0; jj < 12; jj++)
            arow[lane + jj * 32] = lreg[jj] * inv;
    }
}

// ---------------- pairwise: block per (i, c-half) ----------------
__global__ void pairwise_kernel(const float* __restrict__ z) {
    int i = blockIdx.x;
    int ch = blockIdx.y;
    int tid = threadIdx.x;   // 256
    __shared__ float att_s[N_HEAD][N_RES];
    __shared__ float4 part[8][N_HEAD][16];
    for (int idx = tid; idx < N_HEAD * N_RES; idx += 256) {
        int h = idx / N_RES, j = idx % N_RES;
        att_s[h][j] = g_att[((size_t)h * N_RES + i) * N_RES + j];
    }
    __syncthreads();
    int c4 = tid & 15;
    int jr = tid >> 4;
    const float4* zp = (const float4*)(z + (size_t)i * N_RES * C_Z) + ch * 16 + c4;
    float acc[N_HEAD][4];
    #pragma unroll
    for (int h = 0; h < N_HEAD; h++) {
        acc[h][0] = 0.f; acc[h][1] = 0.f; acc[h][2] = 0.f; acc[h][3] = 0.f;
    }
    for (int j = jr; j < N_RES; j += 16) {
        float4 zv = zp[j * 32];
        #pragma unroll
        for (int h = 0; h < N_HEAD; h++) {
            float a = att_s[h][j];
            acc[h][0] += a * zv.x; acc[h][1] += a * zv.y;
            acc[h][2] += a * zv.z; acc[h][3] += a * zv.w;
        }
    }
    #pragma unroll
    for (int h = 0; h < N_HEAD; h++) {
        #pragma unroll
        for (int q = 0; q < 4; q++)
            acc[h][q] += __shfl_xor_sync(0xffffffffu, acc[h][q], 16);
    }
    int w = tid >> 5;
    if ((tid & 16) == 0) {
        #pragma unroll
        for (int h = 0; h < N_HEAD; h++)
            part[w][h][c4] = make_float4(acc[h][0], acc[h][1], acc[h][2], acc[h][3]);
    }
    __syncthreads();
    if (tid < N_HEAD * 16) {
        int h = tid >> 4, cc = tid & 15;
        float4 r = part[0][h][cc];
        #pragma unroll
        for (int w2 = 1; w2 < 8; w2++) {
            float4 q = part[w2][h][cc];
            r.x += q.x; r.y += q.y; r.z += q.z; r.w += q.w;
        }
        *(float4*)&g_cat[(size_t)i * 2112 + 576 + h * C_Z + ch * 64 + cc * 4] = r;
    }
}

// ---------------- eo = att[h] @ [v|vt] (vt built inline), fused inverse warp/norm/concat ----------------
__global__ void vatt_post(const float* __restrict__ Tg) {
    int h = blockIdx.y;
    int i0 = blockIdx.x * 32;
    __shared__ float at[32][33];
    __shared__ float vc[32][41];
    __shared__ float eo_s[32][41];
    int tid = threadIdx.x;   // 320
    int col = tid % 40, rgrp = tid / 40;
    float acc[4] = {0.f, 0.f, 0.f, 0.f};
    for (int j0 = 0; j0 < N_RES; j0 += 32) {
        for (int idx = tid; idx < 1024; idx += 320) {
            int r = idx / 32, c = idx % 32;
            at[r][c] = g_att[((size_t)h * N_RES + i0 + r) * N_RES + j0 + c];
        }
        for (int idx = tid; idx < 1280; idx += 320) {
            int r = idx / 40, c = idx % 40;
            int j = j0 + r;
            float val;
            if (c < CDIM) {
                val = g_proj[(size_t)j * NP + 384 + h * CDIM + c];
            } else {
                int k = (c - CDIM) / 3, d = (c - CDIM) % 3;
                const float* pj = &g_proj[(size_t)j * NP + 864 + h * N_PV + k];
                float4 Tr = *(const float4*)&Tg[j * 16 + d * 4];
                val = Tr.x * pj[0] + Tr.y * pj[96] + Tr.z * pj[192] + Tr.w;
            }
            vc[r][c] = val;
        }
        __syncthreads();
        #pragma unroll 8
        for (int jj = 0; jj < 32; jj++) {
            float b = vc[jj][col];
            #pragma unroll
            for (int rr = 0; rr < 4; rr++) acc[rr] += at[rgrp + rr * 8][jj] * b;
        }
        __syncthreads();
    }
    #pragma unroll
    for (int rr = 0; rr < 4; rr++)
        eo_s[rgrp + rr * 8][col] = acc[rr];
    __syncthreads();
    if (tid < 32) {
        int i = i0 + tid;
        const float* e = eo_s[tid];
        float* catp = &g_cat[(size_t)i * 2112];
        #pragma unroll
        for (int c = 0; c < CDIM; c++) catp[h * CDIM + c] = e[c];
        float R[9], tv[3];
        #pragma unroll
        for (int d = 0; d < 9; d++) R[d] = Tg[i * 16 + (d / 3) * 4 + (d % 3)];
        #pragma unroll
        for (int d = 0; d < 3; d++) tv[d] = Tg[i * 16 + d * 4 + 3];
        #pragma unroll
        for (int k = 0; k < N_PV; k++) {
            float px = e[16 + k * 3 + 0] - tv[0];
            float py = e[16 + k * 3 + 1] - tv[1];
            float pz = e[16 + k * 3 + 2] - tv[2];
            float lx = R[0] * px + R[3] * py + R[6] * pz;
            float ly = R[1] * px + R[4] * py + R[7] * pz;
            float lz = R[2] * px + R[5] * py + R[8] * pz;
            catp[192 + 0 * 96 + h * N_PV + k] = lx;
            catp[192 + 1 * 96 + h * N_PV + k] = ly;
            catp[192 + 2 * 96 + h * N_PV + k] = lz;
            catp[480 + h * N_PV + k] = sqrtf(lx * lx + ly * ly + lz * lz);
        }
    }
}

extern "C" void kernel_launch(void* const* d_in, const int* in_sizes, int n_in,
                              void* d_out, int out_size) {
    const float* s   = (const float*)d_in[0];
    const float* z   = (const float*)d_in[1];
    const float* T   = (const float*)d_in[2];
    const float* Wq  = (const float*)d_in[3];
    const float* bq  = (const float*)d_in[4];
    const float* Wk  = (const float*)d_in[5];
    const float* bk  = (const float*)d_in[6];
    const float* Wv  = (const float*)d_in[7];
    const float* bv  = (const float*)d_in[8];
    const float* Wqp = (const float*)d_in[9];
    const float* bqp = (const float*)d_in[10];
    const float* Wkp = (const float*)d_in[11];
    const float* bkp = (const float*)d_in[12];
    const float* Wvp = (const float*)d_in[13];
    const float* bvp = (const float*)d_in[14];
    const float* Wb  = (const float*)d_in[15];
    const float* bb  = (const float*)d_in[16];
    const float* Wo  = (const float*)d_in[17];
    const float* bo  = (const float*)d_in[18];
    const float* hw  = (const float*)d_in[19];
    float* out = (float*)d_out;

    float *p_proj, *p_Wcat, *p_bcat, *p_cat, *p_part;
    cudaGetSymbolAddress((void**)&p_proj, g_proj);
    cudaGetSymbolAddress((void**)&p_Wcat, g_Wcat);
    cudaGetSymbolAddress((void**)&p_bcat, g_bcat);
    cudaGetSymbolAddress((void**)&p_cat,  g_cat);
    cudaGetSymbolAddress((void**)&p_part, g_part);

    static bool attr_set = false;
    if (!attr_set) {
        cudaFuncSetAttribute(bias_mma, cudaFuncAttributeMaxDynamicSharedMemorySize, BIAS_SMEM_BYTES);
        attr_set = true;
    }

    // 1) concat weights + Wb tf32 split
    prep_w<<<(C_S * NP + NP + C_Z * 16 + 255) / 256, 256>>>(Wq, Wk, Wv, Wqp, Wkp, Wvp,
                                                            bq, bk, bv, bqp, bkp, bvp, Wb);
    // 2) all six projections in one tf32 GEMM: s(384x384) @ Wcat(384x1152)
    gemm_tf32<<<dim3(NP / 64, N_RES / 128, 1), 256>>>(s, C_S, p_Wcat, NP, p_bcat, p_proj, NP, C_S);
    // 3) bias from z via tensor cores, smem-staged coalesced loads (75 MB stream)
    bias_mma<<<NROWS / 128, 256, BIAS_SMEM_BYTES>>>(z, bb);
    // 4) tiled attention + softmax (expanded distance form)  <-- profiled slot
    attn_fused<<<dim3(N_RES / 32, N_HEAD), 256>>>(hw, T);
    // 5) pairwise (writes cat[576:2112)) — second 75 MB z stream, c-split x2
    pairwise_kernel<<<dim3(N_RES, 2), 256>>>(z);
    // 6) att @ [v|vt] (vt inline) + fused inverse warp/norm/concat (writes cat[0:576))
    vatt_post<<<dim3(12, 12), 320>>>(T);
    // 7) final projection: cat(384x2112) @ Wo(2112x384), tf32 split-K=6
    gemm_tf32<<<dim3(C_S / 64, N_RES / 128, KSPLIT), 256>>>(p_cat, 2112, Wo, C_S, nullptr, p_part, C_S, 2112 / KSPLIT);
    reduce_out<<<(N_RES * C_S / 4 + 255) / 256, 256>>>(bo, out);
}